// round 4
// baseline (speedup 1.0000x reference)
#include <cuda_runtime.h>
#include <math.h>

#define BTCH 2
#define SEQ  2048
#define DIM  1024
#define NH   16
#define HDM  64
#define NTOK (BTCH*SEQ)

// Scratch (device globals: no allocation allowed in kernel_launch)
__device__ float g_q[NTOK*DIM];
__device__ float g_k[NTOK*DIM];
__device__ float g_v[NTOK*DIM];
__device__ float g_att[NTOK*DIM];

// ---------------------------------------------------------------------------
// SGEMM + bias: C[M,N] = A[M,K] @ W[K,N] + bias,  M=4096, N=K=1024
// 128x128 block tile, BK=8, 256 threads, 8x8 per thread (split 4+4 @ stride 64)
// ---------------------------------------------------------------------------
__global__ __launch_bounds__(256, 2)
void sgemm_bias(const float* __restrict__ A, const float* __restrict__ W,
                const float* __restrict__ bias, float* __restrict__ C) {
    const int K = DIM, N = DIM;
    __shared__ float As[2][8][128];   // transposed: As[k][m]
    __shared__ float Bs[2][8][128];   // Bs[k][n]

    int tid = threadIdx.x;
    int m0 = blockIdx.y * 128;
    int n0 = blockIdx.x * 128;

    int aRow = tid >> 1;            // 0..127
    int aCol = (tid & 1) * 4;       // 0 or 4
    int bRow = tid >> 5;            // 0..7
    int bCol = (tid & 31) * 4;      // 0..124
    int ty = tid >> 4, tx = tid & 15;

    float c[8][8];
    #pragma unroll
    for (int i = 0; i < 8; i++)
        #pragma unroll
        for (int j = 0; j < 8; j++) c[i][j] = 0.f;

    // preload tile k0=0
    {
        float4 a = *(const float4*)&A[(size_t)(m0 + aRow) * K + aCol];
        As[0][aCol+0][aRow] = a.x; As[0][aCol+1][aRow] = a.y;
        As[0][aCol+2][aRow] = a.z; As[0][aCol+3][aRow] = a.w;
        float4 b = *(const float4*)&W[(size_t)bRow * N + n0 + bCol];
        *(float4*)&Bs[0][bRow][bCol] = b;
    }
    __syncthreads();

    int st = 0;
    for (int k0 = 0; k0 < K; k0 += 8) {
        float4 an, bn;
        bool has = (k0 + 8 < K);
        if (has) {
            an = *(const float4*)&A[(size_t)(m0 + aRow) * K + k0 + 8 + aCol];
            bn = *(const float4*)&W[(size_t)(k0 + 8 + bRow) * N + n0 + bCol];
        }
        #pragma unroll
        for (int kk = 0; kk < 8; kk++) {
            float4 a0 = *(float4*)&As[st][kk][ty*4];
            float4 a1 = *(float4*)&As[st][kk][64 + ty*4];
            float4 b0 = *(float4*)&Bs[st][kk][tx*4];
            float4 b1 = *(float4*)&Bs[st][kk][64 + tx*4];
            float av[8] = {a0.x,a0.y,a0.z,a0.w,a1.x,a1.y,a1.z,a1.w};
            float bv[8] = {b0.x,b0.y,b0.z,b0.w,b1.x,b1.y,b1.z,b1.w};
            #pragma unroll
            for (int i = 0; i < 8; i++)
                #pragma unroll
                for (int j = 0; j < 8; j++)
                    c[i][j] += av[i] * bv[j];
        }
        if (has) {
            As[st^1][aCol+0][aRow] = an.x; As[st^1][aCol+1][aRow] = an.y;
            As[st^1][aCol+2][aRow] = an.z; As[st^1][aCol+3][aRow] = an.w;
            *(float4*)&Bs[st^1][bRow][bCol] = bn;
            __syncthreads();
            st ^= 1;
        }
    }

    float4 bias0 = *(const float4*)&bias[n0 + tx*4];
    float4 bias1 = *(const float4*)&bias[n0 + 64 + tx*4];
    #pragma unroll
    for (int i = 0; i < 8; i++) {
        int row = m0 + ((i < 4) ? (ty*4 + i) : (64 + ty*4 + i - 4));
        float4 r0 = make_float4(c[i][0] + bias0.x, c[i][1] + bias0.y,
                                c[i][2] + bias0.z, c[i][3] + bias0.w);
        float4 r1 = make_float4(c[i][4] + bias1.x, c[i][5] + bias1.y,
                                c[i][6] + bias1.z, c[i][7] + bias1.w);
        *(float4*)&C[(size_t)row * N + n0 + tx*4]      = r0;
        *(float4*)&C[(size_t)row * N + n0 + 64 + tx*4] = r1;
    }
}

// ---------------------------------------------------------------------------
// Flash attention, fp32, full (non-causal) softmax.
// One block: one (b,h), 64 query rows. Loop over 64-row key tiles.
// Q,K stored transposed in smem ([hd][row]); P overlays K buffer (48KB total).
// ---------------------------------------------------------------------------
__global__ __launch_bounds__(256, 4)
void flash_attn(const float* __restrict__ Qg, const float* __restrict__ Kg,
                const float* __restrict__ Vg, float* __restrict__ Og) {
    __shared__ float Qs[64][64];     // [hd][q]
    __shared__ float KsPs[64*64];    // K: [hd][k]  then reused as P: [q][k]
    __shared__ float Vs[64][64];     // [k][hd]

    int tid = threadIdx.x;
    int ty = tid >> 4, tx = tid & 15;
    int bh = blockIdx.y;
    int b = bh / NH, h = bh % NH;
    int q0 = blockIdx.x * 64;

    const float scale = 0.125f;  // 1/sqrt(64)

    // Load Q tile once (transposed into smem)
    {
        const float* Qp = Qg + (size_t)(b*SEQ + q0) * DIM + h*HDM;
        #pragma unroll
        for (int it = 0; it < 4; it++) {
            int idx4 = tid + it * 256;       // 0..1023
            int r = idx4 >> 4;
            int cc = (idx4 & 15) * 4;
            float4 v = *(const float4*)&Qp[(size_t)r * DIM + cc];
            Qs[cc+0][r] = v.x; Qs[cc+1][r] = v.y;
            Qs[cc+2][r] = v.z; Qs[cc+3][r] = v.w;
        }
    }

    float o[4][4];
    float m_i[4], l_i[4];
    #pragma unroll
    for (int i = 0; i < 4; i++) {
        m_i[i] = -1e30f; l_i[i] = 0.f;
        #pragma unroll
        for (int j = 0; j < 4; j++) o[i][j] = 0.f;
    }

    for (int k0 = 0; k0 < SEQ; k0 += 64) {
        __syncthreads();  // previous PV reads of Vs / P writes done
        // Load K (transposed) and V tiles
        {
            const float* Kp = Kg + (size_t)(b*SEQ + k0) * DIM + h*HDM;
            const float* Vp = Vg + (size_t)(b*SEQ + k0) * DIM + h*HDM;
            #pragma unroll
            for (int it = 0; it < 4; it++) {
                int idx4 = tid + it * 256;
                int r = idx4 >> 4;
                int cc = (idx4 & 15) * 4;
                float4 vk = *(const float4*)&Kp[(size_t)r * DIM + cc];
                KsPs[(cc+0)*64 + r] = vk.x; KsPs[(cc+1)*64 + r] = vk.y;
                KsPs[(cc+2)*64 + r] = vk.z; KsPs[(cc+3)*64 + r] = vk.w;
                float4 vv = *(const float4*)&Vp[(size_t)r * DIM + cc];
                *(float4*)&Vs[r][cc] = vv;
            }
        }
        __syncthreads();

        // S = scale * Q K^T  (thread tile: rows 4*ty+i, cols 4*tx+j)
        float s[4][4];
        #pragma unroll
        for (int i = 0; i < 4; i++)
            #pragma unroll
            for (int j = 0; j < 4; j++) s[i][j] = 0.f;

        #pragma unroll 8
        for (int kk = 0; kk < 64; kk++) {
            float4 q4 = *(float4*)&Qs[kk][ty*4];
            float4 k4 = *(float4*)&KsPs[kk*64 + tx*4];
            float qv[4] = {q4.x, q4.y, q4.z, q4.w};
            float kv[4] = {k4.x, k4.y, k4.z, k4.w};
            #pragma unroll
            for (int i = 0; i < 4; i++)
                #pragma unroll
                for (int j = 0; j < 4; j++)
                    s[i][j] += qv[i] * kv[j];
        }

        // Online softmax per row (reduce over the 16 tx lanes)
        #pragma unroll
        for (int i = 0; i < 4; i++) {
            float tm = s[i][0] * scale;
            #pragma unroll
            for (int j = 1; j < 4; j++) tm = fmaxf(tm, s[i][j] * scale);
            #pragma unroll
            for (int d = 1; d < 16; d <<= 1)
                tm = fmaxf(tm, __shfl_xor_sync(0xffffffffu, tm, d));
            float mnew = fmaxf(m_i[i], tm);
            float corr = __expf(m_i[i] - mnew);
            m_i[i] = mnew;
            float rs = 0.f;
            #pragma unroll
            for (int j = 0; j < 4; j++) {
                float p = __expf(s[i][j] * scale - mnew);
                s[i][j] = p;
                rs += p;
            }
            #pragma unroll
            for (int d = 1; d < 16; d <<= 1)
                rs += __shfl_xor_sync(0xffffffffu, rs, d);
            l_i[i] = l_i[i] * corr + rs;
            #pragma unroll
            for (int j = 0; j < 4; j++) o[i][j] *= corr;
        }

        __syncthreads();  // all S reads of K done; reuse buffer as P
        #pragma unroll
        for (int i = 0; i < 4; i++) {
            float4 pv = make_float4(s[i][0], s[i][1], s[i][2], s[i][3]);
            *(float4*)&KsPs[(ty*4 + i)*64 + tx*4] = pv;
        }
        __syncthreads();

        // O += P @ V   (thread tile: q rows 4*ty+i, hd cols 4*tx+j)
        #pragma unroll 8
        for (int kk = 0; kk < 64; kk++) {
            float4 v4 = *(float4*)&Vs[kk][tx*4];
            float vv[4] = {v4.x, v4.y, v4.z, v4.w};
            #pragma unroll
            for (int i = 0; i < 4; i++) {
                float p = KsPs[(ty*4 + i)*64 + kk];
                #pragma unroll
                for (int j = 0; j < 4; j++)
                    o[i][j] += p * vv[j];
            }
        }
    }

    // Epilogue: normalize and write [B,S,H,HD] == [B,S,D] layout
    #pragma unroll
    for (int i = 0; i < 4; i++) {
        float inv = 1.f / l_i[i];
        int row = b*SEQ + q0 + ty*4 + i;
        float4 r = make_float4(o[i][0]*inv, o[i][1]*inv, o[i][2]*inv, o[i][3]*inv);
        *(float4*)&Og[(size_t)row * DIM + h*HDM + tx*4] = r;
    }
}

extern "C" void kernel_launch(void* const* d_in, const int* in_sizes, int n_in,
                              void* d_out, int out_size) {
    const float* query = (const float*)d_in[0];
    const float* key   = (const float*)d_in[1];
    const float* value = (const float*)d_in[2];
    const float* Wq = (const float*)d_in[3];
    const float* bq = (const float*)d_in[4];
    const float* Wk = (const float*)d_in[5];
    const float* bk = (const float*)d_in[6];
    const float* Wv = (const float*)d_in[7];
    const float* bv = (const float*)d_in[8];
    const float* Wo = (const float*)d_in[9];
    const float* bo = (const float*)d_in[10];
    float* out = (float*)d_out;

    float *gq = nullptr, *gk = nullptr, *gv = nullptr, *ga = nullptr;
    cudaGetSymbolAddress((void**)&gq, g_q);
    cudaGetSymbolAddress((void**)&gk, g_k);
    cudaGetSymbolAddress((void**)&gv, g_v);
    cudaGetSymbolAddress((void**)&ga, g_att);

    dim3 gg(DIM/128, NTOK/128);     // (8, 32)
    sgemm_bias<<<gg, 256>>>(query, Wq, bq, gq);
    sgemm_bias<<<gg, 256>>>(key,   Wk, bk, gk);
    sgemm_bias<<<gg, 256>>>(value, Wv, bv, gv);

    dim3 ag(SEQ/64, BTCH*NH);       // (32, 32)
    flash_attn<<<ag, 256>>>(gq, gk, gv, ga);

    sgemm_bias<<<gg, 256>>>(ga, Wo, bo, out);
}

// round 8
// speedup vs baseline: 1.1856x; 1.1856x over previous
#include <cuda_runtime.h>
#include <cuda_bf16.h>
#include <mma.h>
#include <cstdint>
#include <math.h>

using namespace nvcuda;

#define BTCH 2
#define SEQ  2048
#define DIM  1024
#define NH   16
#define HDM  64
#define NTOK (BTCH*SEQ)

#define PADA 40    // 32 + 8 bf16 pad (k-dim rows for A tiles)
#define PADB 136   // 128 + 8 bf16 pad (n-dim rows for B tiles)

// Scratch (device globals: no allocation allowed in kernel_launch)
__device__ float g_q[NTOK*DIM];
__device__ float g_k[NTOK*DIM];
__device__ float g_v[NTOK*DIM];
__device__ float g_att[NTOK*DIM];

// pack 4 floats as 4 bf16 (2x bf162) -> uint2
__device__ __forceinline__ uint2 pack4_bf16(float a, float b, float c, float d) {
    __nv_bfloat162 lo = __floats2bfloat162_rn(a, b);
    __nv_bfloat162 hi = __floats2bfloat162_rn(c, d);
    uint2 r;
    r.x = *reinterpret_cast<uint32_t*>(&lo);
    r.y = *reinterpret_cast<uint32_t*>(&hi);
    return r;
}

// ---------------------------------------------------------------------------
// WMMA bf16 GEMM + bias with 3xBF16 compensation:
//   C[M,N] = A[M,K] @ W[K,N] + bias,  M=4096, N=K=1024
// CTA 128x128, K-chunk 32, 256 threads = 8 warps (4M x 2N), warp tile 32x64.
// acc(fp32) starts at bias; per chunk: acc += Ah*Bh + Ah*Bl + Al*Bh.
// ---------------------------------------------------------------------------
__global__ __launch_bounds__(256, 2)
void gemm_wmma(const float* __restrict__ A, const float* __restrict__ W,
               const float* __restrict__ bias, float* __restrict__ C) {
    __shared__ __align__(16) __nv_bfloat16 Ah[128 * PADA];
    __shared__ __align__(16) __nv_bfloat16 Al[128 * PADA];
    __shared__ __align__(16) __nv_bfloat16 Bh[32 * PADB];
    __shared__ __align__(16) __nv_bfloat16 Bl[32 * PADB];
    __shared__ __align__(16) float biasS[16 * 128];   // 16 replicated rows

    int tid  = threadIdx.x;
    int warp = tid >> 5;
    int wm   = warp >> 1;          // 0..3  (M)
    int wn   = warp & 1;           // 0..1  (N)
    int m0 = blockIdx.y * 128;
    int n0 = blockIdx.x * 128;

    // Stage bias as a 16-row replicated tile, then init accumulators from it.
    for (int i = tid; i < 16 * 128; i += 256)
        biasS[i] = bias[n0 + (i & 127)];
    __syncthreads();

    wmma::fragment<wmma::accumulator, 16, 16, 16, float> acc[2][4];
    #pragma unroll
    for (int mi = 0; mi < 2; mi++)
        #pragma unroll
        for (int ni = 0; ni < 4; ni++)
            wmma::load_matrix_sync(acc[mi][ni], biasS + wn * 64 + ni * 16,
                                   128, wmma::mem_row_major);

    for (int c = 0; c < 32; c++) {
        __syncthreads();   // prior chunk's fragment loads done before overwrite

        // ---- load A chunk [128 m][32 k], split hi/lo ----
        #pragma unroll
        for (int it = 0; it < 4; it++) {
            int idx = it * 256 + tid;       // 0..1023
            int row = idx >> 3;
            int col = (idx & 7) * 4;
            float4 a = *(const float4*)&A[(size_t)(m0 + row) * DIM + c * 32 + col];
            float hx = __bfloat162float(__float2bfloat16(a.x));
            float hy = __bfloat162float(__float2bfloat16(a.y));
            float hz = __bfloat162float(__float2bfloat16(a.z));
            float hw = __bfloat162float(__float2bfloat16(a.w));
            *(uint2*)&Ah[row * PADA + col] = pack4_bf16(hx, hy, hz, hw);
            *(uint2*)&Al[row * PADA + col] =
                pack4_bf16(a.x - hx, a.y - hy, a.z - hz, a.w - hw);
        }
        // ---- load B chunk [32 k][128 n] direct from W (row-major), split ----
        #pragma unroll
        for (int it = 0; it < 4; it++) {
            int idx = it * 256 + tid;
            int row = idx >> 5;             // 0..31 (k)
            int col = (idx & 31) * 4;       // 0..124 (n)
            float4 b = *(const float4*)&W[(size_t)(c * 32 + row) * DIM + n0 + col];
            float hx = __bfloat162float(__float2bfloat16(b.x));
            float hy = __bfloat162float(__float2bfloat16(b.y));
            float hz = __bfloat162float(__float2bfloat16(b.z));
            float hw = __bfloat162float(__float2bfloat16(b.w));
            *(uint2*)&Bh[row * PADB + col] = pack4_bf16(hx, hy, hz, hw);
            *(uint2*)&Bl[row * PADB + col] =
                pack4_bf16(b.x - hx, b.y - hy, b.z - hz, b.w - hw);
        }
        __syncthreads();

        // ---- MMA: 2 k-steps of 16 ----
        #pragma unroll
        for (int kk = 0; kk < 2; kk++) {
            wmma::fragment<wmma::matrix_a, 16, 16, 16, __nv_bfloat16, wmma::row_major> ah[2], al[2];
            #pragma unroll
            for (int mi = 0; mi < 2; mi++) {
                const __nv_bfloat16* ap = Ah + (wm * 32 + mi * 16) * PADA + kk * 16;
                const __nv_bfloat16* lp = Al + (wm * 32 + mi * 16) * PADA + kk * 16;
                wmma::load_matrix_sync(ah[mi], ap, PADA);
                wmma::load_matrix_sync(al[mi], lp, PADA);
            }
            #pragma unroll
            for (int ni = 0; ni < 4; ni++) {
                wmma::fragment<wmma::matrix_b, 16, 16, 16, __nv_bfloat16, wmma::row_major> bh, bl;
                const __nv_bfloat16* bp = Bh + (kk * 16) * PADB + wn * 64 + ni * 16;
                const __nv_bfloat16* qp = Bl + (kk * 16) * PADB + wn * 64 + ni * 16;
                wmma::load_matrix_sync(bh, bp, PADB);
                wmma::load_matrix_sync(bl, qp, PADB);
                #pragma unroll
                for (int mi = 0; mi < 2; mi++) {
                    wmma::mma_sync(acc[mi][ni], ah[mi], bh, acc[mi][ni]);
                    wmma::mma_sync(acc[mi][ni], ah[mi], bl, acc[mi][ni]);
                    wmma::mma_sync(acc[mi][ni], al[mi], bh, acc[mi][ni]);
                }
            }
        }
    }

    // ---- store ----
    #pragma unroll
    for (int mi = 0; mi < 2; mi++)
        #pragma unroll
        for (int ni = 0; ni < 4; ni++)
            wmma::store_matrix_sync(
                C + (size_t)(m0 + wm * 32 + mi * 16) * DIM + n0 + wn * 64 + ni * 16,
                acc[mi][ni], DIM, wmma::mem_row_major);
}

// ---------------------------------------------------------------------------
// Flash attention, fp32 (unchanged from passing baseline)
// ---------------------------------------------------------------------------
__global__ __launch_bounds__(256, 4)
void flash_attn(const float* __restrict__ Qg, const float* __restrict__ Kg,
                const float* __restrict__ Vg, float* __restrict__ Og) {
    __shared__ float Qs[64][64];
    __shared__ float KsPs[64*64];
    __shared__ float Vs[64][64];

    int tid = threadIdx.x;
    int ty = tid >> 4, tx = tid & 15;
    int bh = blockIdx.y;
    int b = bh / NH, h = bh % NH;
    int q0 = blockIdx.x * 64;

    const float scale = 0.125f;

    {
        const float* Qp = Qg + (size_t)(b*SEQ + q0) * DIM + h*HDM;
        #pragma unroll
        for (int it = 0; it < 4; it++) {
            int idx4 = tid + it * 256;
            int r = idx4 >> 4;
            int cc = (idx4 & 15) * 4;
            float4 v = *(const float4*)&Qp[(size_t)r * DIM + cc];
            Qs[cc+0][r] = v.x; Qs[cc+1][r] = v.y;
            Qs[cc+2][r] = v.z; Qs[cc+3][r] = v.w;
        }
    }

    float o[4][4];
    float m_i[4], l_i[4];
    #pragma unroll
    for (int i = 0; i < 4; i++) {
        m_i[i] = -1e30f; l_i[i] = 0.f;
        #pragma unroll
        for (int j = 0; j < 4; j++) o[i][j] = 0.f;
    }

    for (int k0 = 0; k0 < SEQ; k0 += 64) {
        __syncthreads();
        {
            const float* Kp = Kg + (size_t)(b*SEQ + k0) * DIM + h*HDM;
            const float* Vp = Vg + (size_t)(b*SEQ + k0) * DIM + h*HDM;
            #pragma unroll
            for (int it = 0; it < 4; it++) {
                int idx4 = tid + it * 256;
                int r = idx4 >> 4;
                int cc = (idx4 & 15) * 4;
                float4 vk = *(const float4*)&Kp[(size_t)r * DIM + cc];
                KsPs[(cc+0)*64 + r] = vk.x; KsPs[(cc+1)*64 + r] = vk.y;
                KsPs[(cc+2)*64 + r] = vk.z; KsPs[(cc+3)*64 + r] = vk.w;
                float4 vv = *(const float4*)&Vp[(size_t)r * DIM + cc];
                *(float4*)&Vs[r][cc] = vv;
            }
        }
        __syncthreads();

        float s[4][4];
        #pragma unroll
        for (int i = 0; i < 4; i++)
            #pragma unroll
            for (int j = 0; j < 4; j++) s[i][j] = 0.f;

        #pragma unroll 8
        for (int kk = 0; kk < 64; kk++) {
            float4 q4 = *(float4*)&Qs[kk][ty*4];
            float4 k4 = *(float4*)&KsPs[kk*64 + tx*4];
            float qv[4] = {q4.x, q4.y, q4.z, q4.w};
            float kv[4] = {k4.x, k4.y, k4.z, k4.w};
            #pragma unroll
            for (int i = 0; i < 4; i++)
                #pragma unroll
                for (int j = 0; j < 4; j++)
                    s[i][j] += qv[i] * kv[j];
        }

        #pragma unroll
        for (int i = 0; i < 4; i++) {
            float tm = s[i][0] * scale;
            #pragma unroll
            for (int j = 1; j < 4; j++) tm = fmaxf(tm, s[i][j] * scale);
            #pragma unroll
            for (int d = 1; d < 16; d <<= 1)
                tm = fmaxf(tm, __shfl_xor_sync(0xffffffffu, tm, d));
            float mnew = fmaxf(m_i[i], tm);
            float corr = __expf(m_i[i] - mnew);
            m_i[i] = mnew;
            float rs = 0.f;
            #pragma unroll
            for (int j = 0; j < 4; j++) {
                float p = __expf(s[i][j] * scale - mnew);
                s[i][j] = p;
                rs += p;
            }
            #pragma unroll
            for (int d = 1; d < 16; d <<= 1)
                rs += __shfl_xor_sync(0xffffffffu, rs, d);
            l_i[i] = l_i[i] * corr + rs;
            #pragma unroll
            for (int j = 0; j < 4; j++) o[i][j] *= corr;
        }

        __syncthreads();
        #pragma unroll
        for (int i = 0; i < 4; i++) {
            float4 pv = make_float4(s[i][0], s[i][1], s[i][2], s[i][3]);
            *(float4*)&KsPs[(ty*4 + i)*64 + tx*4] = pv;
        }
        __syncthreads();

        #pragma unroll 8
        for (int kk = 0; kk < 64; kk++) {
            float4 v4 = *(float4*)&Vs[kk][tx*4];
            float vv[4] = {v4.x, v4.y, v4.z, v4.w};
            #pragma unroll
            for (int i = 0; i < 4; i++) {
                float p = KsPs[(ty*4 + i)*64 + kk];
                #pragma unroll
                for (int j = 0; j < 4; j++)
                    o[i][j] += p * vv[j];
            }
        }
    }

    #pragma unroll
    for (int i = 0; i < 4; i++) {
        float inv = 1.f / l_i[i];
        int row = b*SEQ + q0 + ty*4 + i;
        float4 r = make_float4(o[i][0]*inv, o[i][1]*inv, o[i][2]*inv, o[i][3]*inv);
        *(float4*)&Og[(size_t)row * DIM + h*HDM + tx*4] = r;
    }
}

extern "C" void kernel_launch(void* const* d_in, const int* in_sizes, int n_in,
                              void* d_out, int out_size) {
    const float* query = (const float*)d_in[0];
    const float* key   = (const float*)d_in[1];
    const float* value = (const float*)d_in[2];
    const float* Wq = (const float*)d_in[3];
    const float* bq = (const float*)d_in[4];
    const float* Wk = (const float*)d_in[5];
    const float* bk = (const float*)d_in[6];
    const float* Wv = (const float*)d_in[7];
    const float* bv = (const float*)d_in[8];
    const float* Wo = (const float*)d_in[9];
    const float* bo = (const float*)d_in[10];
    float* out = (float*)d_out;

    float *gq, *gk, *gv, *ga;
    cudaGetSymbolAddress((void**)&gq, g_q);
    cudaGetSymbolAddress((void**)&gk, g_k);
    cudaGetSymbolAddress((void**)&gv, g_v);
    cudaGetSymbolAddress((void**)&ga, g_att);

    dim3 gg(DIM/128, NTOK/128);     // (8, 32)
    gemm_wmma<<<gg, 256>>>(query, Wq, bq, gq);
    gemm_wmma<<<gg, 256>>>(key,   Wk, bk, gk);
    gemm_wmma<<<gg, 256>>>(value, Wv, bv, gv);

    dim3 ag(SEQ/64, BTCH*NH);       // (32, 32)
    flash_attn<<<ag, 256>>>(gq, gk, gv, ga);

    gemm_wmma<<<gg, 256>>>(ga, Wo, bo, out);
}